// round 6
// baseline (speedup 1.0000x reference)
#include <cuda_runtime.h>
#include <cuda_bf16.h>
#include <cstddef>

// Problem constants (fixed shapes per reference)
constexpr int B_ = 16;
constexpr int C_ = 256;
constexpr int L_ = 8192;
constexpr int D_ = 512;   // d_inner
constexpr int A_ = 64;    // att_dim

// Single fused kernel. One block = (one b, 32 consecutive l). 256 threads =
// 8 c-groups x 32 l. Each thread keeps its 32 h values in registers -> h_v
// read exactly once. Each block also derives u[d] = w_out @ wv (L2-hot,
// 128KB shared by all blocks) and coef = <wq,wk>/8 itself -> no prep kernel.
__global__ void __launch_bounds__(256)
pool_outer_kernel(const float* __restrict__ h_v,
                  const float* __restrict__ wq,
                  const float* __restrict__ wk,
                  const float* __restrict__ wv,
                  const float* __restrict__ w_out,
                  float* __restrict__ out) {
    __shared__ float s_u[D_];
    __shared__ float s_red[256];
    __shared__ float s_red2[256];
    __shared__ float s_sval[32];
    __shared__ __align__(16) float s_pooled[32];
    __shared__ __align__(16) float s_wv[A_];

    const int tid = threadIdx.x;
    const int ll  = tid & 31;   // l within tile
    const int cg  = tid >> 5;   // c-group 0..7

    const int bidx   = blockIdx.x;          // 16 * 256 = 4096 blocks
    const int b      = bidx >> 8;
    const int l_base = (bidx & 255) << 5;

    // stage wv into smem (visible after first barrier)
    if (tid < A_) s_wv[tid] = wv[tid];

    // warp 0: coef = <wq,wk>/8, kept in registers (only warp 0 consumes it)
    float coef = 0.f;
    if (tid < 32) {
        float p = wq[tid] * wk[tid] + wq[tid + 32] * wk[tid + 32];
#pragma unroll
        for (int m = 16; m >= 1; m >>= 1)
            p += __shfl_xor_sync(0xffffffffu, p, m);
        coef = p * 0.125f;  // 1/sqrt(64)
    }

    // ---- single read of h_v: 32 values per thread, coalesced per warp ----
    const float* p = h_v + ((size_t)b * C_ + (size_t)cg * 32) * L_ + l_base + ll;
    float h[32];
#pragma unroll
    for (int i = 0; i < 32; i++) h[i] = __ldcs(p + (size_t)i * L_);

    // ---- mean over C ----
    float sum = 0.f;
#pragma unroll
    for (int i = 0; i < 32; i++) sum += h[i];
    s_red[tid] = sum;
    __syncthreads();
    if (tid < 32) {
        float t = 0.f;
#pragma unroll
        for (int j = 0; j < 8; j++) t += s_red[tid + 32 * j];
        s_sval[tid] = t * ((1.0f / 256.0f) * coef);  // fold mean scale + qk/sqrt(A)
    }
    __syncthreads();

    const float coef2 = s_sval[ll];  // per-l logit scale

    // ---- softmax-weighted sum (max-free: |logit| bounded ~1.2) ----
    float se = 0.f, seh = 0.f;
#pragma unroll
    for (int i = 0; i < 32; i++) {
        float e = __expf(h[i] * coef2);
        se  += e;
        seh += e * h[i];
    }
    s_red[tid]  = se;
    s_red2[tid] = seh;

    // ---- u[d] = sum_a w_out[d,a] * wv[a]; h[] is dead here, regs are free.
    // Each thread does rows tid and tid+256 (L2-hot after wave 1).
    {
        const float4* w0 = reinterpret_cast<const float4*>(w_out + (size_t)tid * A_);
        const float4* w1 = reinterpret_cast<const float4*>(w_out + (size_t)(tid + 256) * A_);
        const float4* v4 = reinterpret_cast<const float4*>(s_wv);
        float a0 = 0.f, a1 = 0.f;
#pragma unroll 4
        for (int j = 0; j < A_ / 4; j++) {
            float4 vv = v4[j];
            float4 r0 = __ldg(&w0[j]);
            float4 r1 = __ldg(&w1[j]);
            a0 += r0.x * vv.x + r0.y * vv.y + r0.z * vv.z + r0.w * vv.w;
            a1 += r1.x * vv.x + r1.y * vv.y + r1.z * vv.z + r1.w * vv.w;
        }
        s_u[tid]       = a0;
        s_u[tid + 256] = a1;
    }
    __syncthreads();

    if (tid < 32) {
        float te = 0.f, teh = 0.f;
#pragma unroll
        for (int j = 0; j < 8; j++) {
            te  += s_red[tid + 32 * j];
            teh += s_red2[tid + 32 * j];
        }
        s_pooled[tid] = teh / te;
    }
    __syncthreads();

    // ---- epilogue: out[b,d,l] = pooled[l] * u[d], float4 streaming stores.
    // pooled float4 held in a register; iterate d by +32.
    const int lq = tid & 7;
    const int d0 = tid >> 3;
    const float4 pv = reinterpret_cast<const float4*>(s_pooled)[lq];
    float4* out4 = reinterpret_cast<float4*>(out + (size_t)b * D_ * L_ + l_base) + lq;
#pragma unroll
    for (int k = 0; k < 16; k++) {
        int d = d0 + 32 * k;
        float ud = s_u[d];
        __stcs(&out4[(size_t)d * (L_ / 4)],
               make_float4(pv.x * ud, pv.y * ud, pv.z * ud, pv.w * ud));
    }
}

extern "C" void kernel_launch(void* const* d_in, const int* in_sizes, int n_in,
                              void* d_out, int out_size) {
    const float* h_v   = (const float*)d_in[0];  // [B, C, L]
    const float* wq    = (const float*)d_in[1];  // [64]
    const float* wk    = (const float*)d_in[2];  // [64]
    const float* wv    = (const float*)d_in[3];  // [64]
    const float* w_out = (const float*)d_in[4];  // [512, 64]
    float* out = (float*)d_out;                  // [B, 512, L]

    pool_outer_kernel<<<B_ * (L_ / 32), 256>>>(h_v, wq, wk, wv, w_out, out);
}

// round 7
// speedup vs baseline: 1.9106x; 1.9106x over previous
#include <cuda_runtime.h>
#include <cuda_bf16.h>
#include <cstddef>

// Problem constants (fixed shapes per reference)
constexpr int B_ = 16;
constexpr int C_ = 256;
constexpr int L_ = 8192;
constexpr int D_ = 512;   // d_inner
constexpr int A_ = 64;    // att_dim

constexpr int GRID_MAIN = 512;           // persistent blocks, single wave
constexpr int TILES_PB  = (B_ * (L_ / 32)) / GRID_MAIN;  // 8 tiles per block

// Scratch: u[d] = sum_a w_out[d,a]*wv[a]; coef = <wq,wk>/sqrt(att_dim)
__device__ float g_u[D_];
__device__ float g_coef;

// 32 blocks x 256 threads (proven R3 prep). Block g computes u[g*16..g*16+16).
__global__ void prep_kernel(const float* __restrict__ wq,
                            const float* __restrict__ wk,
                            const float* __restrict__ wv,
                            const float* __restrict__ w_out) {
    const int t = threadIdx.x;
    const int g = blockIdx.x;
    const int dl   = t >> 4;
    const int part = t & 15;
    const int d = g * 16 + dl;

    const float4* w4  = reinterpret_cast<const float4*>(w_out + (size_t)d * A_);
    const float4  wv4 = reinterpret_cast<const float4*>(wv)[part];
    const float4  a4  = w4[part];
    float acc = a4.x * wv4.x + a4.y * wv4.y + a4.z * wv4.z + a4.w * wv4.w;
#pragma unroll
    for (int m = 1; m < 16; m <<= 1)
        acc += __shfl_xor_sync(0xffffffffu, acc, m);
    if (part == 0) g_u[d] = acc;

    if (g == 0 && t < 32) {
        float p = wq[t] * wk[t] + wq[t + 32] * wk[t + 32];
#pragma unroll
        for (int m = 16; m >= 1; m >>= 1)
            p += __shfl_xor_sync(0xffffffffu, p, m);
        if (t == 0) g_coef = p * 0.125f;  // 1/sqrt(64)
    }
}

// Persistent main kernel. Each block processes TILES_PB tiles of 32 l's,
// double-buffering the 32 per-thread h values in registers: the next tile's
// 32 LDGs are issued as soon as the current tile's h[] goes dead (after the
// exp phase), hiding DRAM latency under barriers + the 256KB store phase.
__global__ void __launch_bounds__(256, 4)
pool_outer_kernel(const float* __restrict__ h_v, float* __restrict__ out) {
    __shared__ float s_u[D_];
    __shared__ float s_red[256];
    __shared__ float s_red2[256];
    __shared__ float s_sval[32];
    __shared__ __align__(16) float s_pooled[32];

    const int tid = threadIdx.x;
    const int ll  = tid & 31;   // l within tile
    const int cg  = tid >> 5;   // c-group 0..7
    const int lq  = tid & 7;    // epilogue: float4 index
    const int d0  = tid >> 3;   // epilogue: starting d

    const float coef = g_coef;
    s_u[tid]       = g_u[tid];
    s_u[tid + 256] = g_u[tid + 256];

    const int bk = blockIdx.x;

    float ha[32], hb[32];

    // prologue: load tile 0
    {
        const int tile = bk;
        const float* p = h_v + ((size_t)(tile >> 8) * C_ + (size_t)cg * 32) * L_
                             + ((tile & 255) << 5) + ll;
#pragma unroll
        for (int i = 0; i < 32; i++) ha[i] = __ldcs(p + (size_t)i * L_);
    }

    // one tile: reduce+exp on h, prefetch next into hn, then store epilogue
    auto process = [&](float (&h)[32], float (&hn)[32], int tile, int next_tile) {
        const int b      = tile >> 8;
        const int l_base = (tile & 255) << 5;

        // mean over C
        float sum = 0.f;
#pragma unroll
        for (int i = 0; i < 32; i++) sum += h[i];
        s_red[tid] = sum;
        __syncthreads();
        if (tid < 32) {
            float t = 0.f;
#pragma unroll
            for (int j = 0; j < 8; j++) t += s_red[tid + 32 * j];
            s_sval[tid] = t * ((1.0f / 256.0f) * coef);
        }
        __syncthreads();

        const float coef2 = s_sval[ll];

        // softmax-weighted sum (max-free: |logit| bounded ~1.2)
        float se = 0.f, seh = 0.f;
#pragma unroll
        for (int i = 0; i < 32; i++) {
            float e = __expf(h[i] * coef2);
            se  += e;
            seh += e * h[i];
        }

        // h[] is dead -> prefetch next tile now (hidden under bars + stores)
        if (next_tile >= 0) {
            const float* pn = h_v + ((size_t)(next_tile >> 8) * C_ + (size_t)cg * 32) * L_
                                  + ((next_tile & 255) << 5) + ll;
#pragma unroll
            for (int i = 0; i < 32; i++) hn[i] = __ldcs(pn + (size_t)i * L_);
        }

        s_red[tid]  = se;
        s_red2[tid] = seh;
        __syncthreads();
        if (tid < 32) {
            float te = 0.f, teh = 0.f;
#pragma unroll
            for (int j = 0; j < 8; j++) {
                te  += s_red[tid + 32 * j];
                teh += s_red2[tid + 32 * j];
            }
            s_pooled[tid] = teh / te;
        }
        __syncthreads();

        // epilogue: out[b,d,l] = pooled[l] * u[d], float4 streaming stores
        const float4 pv = reinterpret_cast<const float4*>(s_pooled)[lq];
        float4* out4 = reinterpret_cast<float4*>(out + (size_t)b * D_ * L_ + l_base) + lq;
#pragma unroll
        for (int k = 0; k < 16; k++) {
            int d = d0 + 32 * k;
            float ud = s_u[d];
            __stcs(&out4[(size_t)d * (L_ / 4)],
                   make_float4(pv.x * ud, pv.y * ud, pv.z * ud, pv.w * ud));
        }
    };

#pragma unroll 1
    for (int tt = 0; tt < TILES_PB; tt += 2) {
        process(ha, hb, bk + tt * GRID_MAIN, bk + (tt + 1) * GRID_MAIN);
        process(hb, ha, bk + (tt + 1) * GRID_MAIN,
                (tt + 2 < TILES_PB) ? (bk + (tt + 2) * GRID_MAIN) : -1);
    }
}

extern "C" void kernel_launch(void* const* d_in, const int* in_sizes, int n_in,
                              void* d_out, int out_size) {
    const float* h_v   = (const float*)d_in[0];  // [B, C, L]
    const float* wq    = (const float*)d_in[1];  // [64]
    const float* wk    = (const float*)d_in[2];  // [64]
    const float* wv    = (const float*)d_in[3];  // [64]
    const float* w_out = (const float*)d_in[4];  // [512, 64]
    float* out = (float*)d_out;                  // [B, 512, L]

    prep_kernel<<<D_ / 16, 256>>>(wq, wk, wv, w_out);
    pool_outer_kernel<<<GRID_MAIN, 256>>>(h_v, out);
}

// round 8
// speedup vs baseline: 2.4500x; 1.2823x over previous
#include <cuda_runtime.h>
#include <cuda_bf16.h>
#include <cstddef>

// Problem constants (fixed shapes per reference)
constexpr int B_ = 16;
constexpr int C_ = 256;
constexpr int L_ = 8192;
constexpr int D_ = 512;   // d_inner
constexpr int A_ = 64;    // att_dim

// Scratch: u[d] = sum_a w_out[d,a]*wv[a]; coef = <wq,wk>/sqrt(att_dim)
__device__ float g_u[D_];
__device__ float g_coef;

// 32 blocks x 256 threads (proven R3 prep). Block g computes u[g*16..g*16+16).
__global__ void prep_kernel(const float* __restrict__ wq,
                            const float* __restrict__ wk,
                            const float* __restrict__ wv,
                            const float* __restrict__ w_out) {
    const int t = threadIdx.x;
    const int g = blockIdx.x;
    const int dl   = t >> 4;
    const int part = t & 15;
    const int d = g * 16 + dl;

    const float4* w4  = reinterpret_cast<const float4*>(w_out + (size_t)d * A_);
    const float4  wv4 = reinterpret_cast<const float4*>(wv)[part];
    const float4  a4  = w4[part];
    float acc = a4.x * wv4.x + a4.y * wv4.y + a4.z * wv4.z + a4.w * wv4.w;
#pragma unroll
    for (int m = 1; m < 16; m <<= 1)
        acc += __shfl_xor_sync(0xffffffffu, acc, m);
    if (part == 0) g_u[d] = acc;

    if (g == 0 && t < 32) {
        float p = wq[t] * wk[t] + wq[t + 32] * wk[t + 32];
#pragma unroll
        for (int m = 16; m >= 1; m >>= 1)
            p += __shfl_xor_sync(0xffffffffu, p, m);
        if (t == 0) g_coef = p * 0.125f;  // 1/sqrt(64)
    }
}

// One block = (one b, 16 consecutive l). 256 threads = 16 c-groups x 16 l.
// Each thread keeps 16 h values in registers -> h_v read exactly once.
// Smaller footprint than the 32-l variant: ~36 regs -> 6-7 CTAs/SM.
__global__ void __launch_bounds__(256, 6)
pool_outer_kernel(const float* __restrict__ h_v, float* __restrict__ out) {
    __shared__ float s_u[D_];
    __shared__ float s_red[256];
    __shared__ float s_red2[256];
    __shared__ float s_sval[16];
    __shared__ __align__(16) float s_pooled[16];

    const int tid = threadIdx.x;
    const int ll  = tid & 15;   // l within tile
    const int cg  = tid >> 4;   // c-group 0..15 (16 c each)

    const int bidx   = blockIdx.x;          // 16 * 512 = 8192 blocks
    const int b      = bidx >> 9;
    const int l_base = (bidx & 511) << 4;

    const float coef = g_coef;

    // stage u into smem (2 per thread)
    s_u[tid]       = g_u[tid];
    s_u[tid + 256] = g_u[tid + 256];

    // ---- single read of h_v: 16 values per thread (imm-offset LDGs) ----
    const float* p = h_v + ((size_t)b * C_ + (size_t)cg * 16) * L_ + l_base + ll;
    float h[16];
#pragma unroll
    for (int i = 0; i < 16; i++) h[i] = __ldcs(p + (size_t)i * L_);

    // ---- mean over C ----
    float sum = 0.f;
#pragma unroll
    for (int i = 0; i < 16; i++) sum += h[i];
    s_red[tid] = sum;
    __syncthreads();
    if (tid < 16) {
        float t = 0.f;
#pragma unroll
        for (int j = 0; j < 16; j++) t += s_red[tid + 16 * j];
        s_sval[tid] = t * ((1.0f / 256.0f) * coef);  // fold mean scale + qk/sqrt(A)
    }
    __syncthreads();

    const float coef2 = s_sval[ll];  // per-l logit scale

    // ---- softmax-weighted sum (max-free: |logit| bounded ~1.2) ----
    float se = 0.f, seh = 0.f;
#pragma unroll
    for (int i = 0; i < 16; i++) {
        float e = __expf(h[i] * coef2);
        se  += e;
        seh += e * h[i];
    }
    s_red[tid]  = se;
    s_red2[tid] = seh;
    __syncthreads();
    if (tid < 16) {
        float te = 0.f, teh = 0.f;
#pragma unroll
        for (int j = 0; j < 16; j++) {
            te  += s_red[tid + 16 * j];
            teh += s_red2[tid + 16 * j];
        }
        s_pooled[tid] = teh / te;
    }
    __syncthreads();

    // ---- epilogue: out[b,d,l] = pooled[l] * u[d], float4 streaming stores.
    // 512 d-rows x 4 float4 = 2048 vec stores per block; 8 per thread.
    const int lq = tid & 3;
    const int d0 = tid >> 2;
    const float4 pv = reinterpret_cast<const float4*>(s_pooled)[lq];
    float4* out4 = reinterpret_cast<float4*>(out + (size_t)b * D_ * L_ + l_base) + lq;
#pragma unroll
    for (int k = 0; k < 8; k++) {
        int d = d0 + 64 * k;
        float ud = s_u[d];
        __stcs(&out4[(size_t)d * (L_ / 4)],
               make_float4(pv.x * ud, pv.y * ud, pv.z * ud, pv.w * ud));
    }
}

extern "C" void kernel_launch(void* const* d_in, const int* in_sizes, int n_in,
                              void* d_out, int out_size) {
    const float* h_v   = (const float*)d_in[0];  // [B, C, L]
    const float* wq    = (const float*)d_in[1];  // [64]
    const float* wk    = (const float*)d_in[2];  // [64]
    const float* wv    = (const float*)d_in[3];  // [64]
    const float* w_out = (const float*)d_in[4];  // [512, 64]
    float* out = (float*)d_out;                  // [B, 512, L]

    prep_kernel<<<D_ / 16, 256>>>(wq, wk, wv, w_out);
    pool_outer_kernel<<<B_ * (L_ / 16), 256>>>(h_v, out);
}